// round 12
// baseline (speedup 1.0000x reference)
#include <cuda_runtime.h>
#include <cuda_bf16.h>
#include <mma.h>
#include <math.h>
#include <cstdint>
#include <cstddef>

using namespace nvcuda;

// Problem dims
#define BB 4
#define SS 2048
#define EE 1024
#define HH 16
#define DD 64
#define FF 4096
#define MM (BB*SS)   // 8192 tokens

// ---------------- scratch (no allocations allowed) ----------------
__device__ float g_ln [MM*EE];
__device__ float g_q  [MM*EE];
__device__ float g_k  [MM*EE];
__device__ float g_v  [MM*EE];
__device__ float g_ctx[MM*EE];
__device__ float g_x1 [MM*EE];
__device__ float g_mid[(size_t)MM*FF];
// tf32-rounded weights: Wq,Wk,Wv,Wo (1M each), W1 (4M), W2 (4M)
__device__ float g_wr [12*1024*1024];

__device__ __forceinline__ float tf32r(float x) {
    float o;
    asm("cvt.rna.tf32.f32 %0, %1;" : "=f"(o) : "f"(x));
    return o;
}

// ---------------- tf32 pre-rounding of weights ----------------
__global__ void round_kernel(const float* __restrict__ src, float* __restrict__ dst, int n4)
{
    int stride = gridDim.x * blockDim.x;
    for (int i = blockIdx.x * blockDim.x + threadIdx.x; i < n4; i += stride) {
        float4 v = ((const float4*)src)[i];
        v.x = tf32r(v.x); v.y = tf32r(v.y); v.z = tf32r(v.z); v.w = tf32r(v.w);
        ((float4*)dst)[i] = v;
    }
}

// ---------------- LayerNorm: one block per row of 1024 ----------------
// Output is tf32-rounded (feeds GEMM A operands only).
__global__ __launch_bounds__(256) void ln_kernel(const float* __restrict__ x,
                                                 const float* __restrict__ g,
                                                 const float* __restrict__ b,
                                                 float* __restrict__ y)
{
    int row = blockIdx.x;
    int tid = threadIdx.x;
    const float4* xr = (const float4*)(x + (size_t)row * EE);
    float4 v = xr[tid];
    float s  = v.x + v.y + v.z + v.w;
    float ss = v.x*v.x + v.y*v.y + v.z*v.z + v.w*v.w;

    __shared__ float rs[8], rss[8];
    #pragma unroll
    for (int o = 16; o > 0; o >>= 1) {
        s  += __shfl_down_sync(0xffffffffu, s,  o);
        ss += __shfl_down_sync(0xffffffffu, ss, o);
    }
    int w = tid >> 5;
    if ((tid & 31) == 0) { rs[w] = s; rss[w] = ss; }
    __syncthreads();
    __shared__ float sh_mean, sh_rstd;
    if (tid == 0) {
        float S1 = 0.f, S2 = 0.f;
        #pragma unroll
        for (int i = 0; i < 8; i++) { S1 += rs[i]; S2 += rss[i]; }
        float mean = S1 * (1.0f / EE);
        float var  = S2 * (1.0f / EE) - mean * mean;
        sh_mean = mean;
        sh_rstd = rsqrtf(var + 1e-5f);
    }
    __syncthreads();
    float mean = sh_mean, rstd = sh_rstd;
    float4 g4 = ((const float4*)g)[tid];
    float4 b4 = ((const float4*)b)[tid];
    float4 o;
    o.x = tf32r((v.x - mean) * rstd * g4.x + b4.x);
    o.y = tf32r((v.y - mean) * rstd * g4.y + b4.y);
    o.z = tf32r((v.z - mean) * rstd * g4.z + b4.z);
    o.w = tf32r((v.w - mean) * rstd * g4.w + b4.w);
    ((float4*)(y + (size_t)row * EE))[tid] = o;
}

// =====================================================================
// TF32 GEMM: C[M,N] = A[M,K] @ W[N,K]^T  (+ fused epilogue)
// Operands are pre-rounded to tf32 -> NO cvt in the hot loop.
// 128x128 block tile, BK=32, cp.async double buffer, 256 threads.
// EPI: 0 = +bias   1 = +bias +res   2 = tf32r(gelu(+bias))
// =====================================================================
#define Bb 128
#define Bn 128
#define Bk 32
#define BKP 40                   // smem K pitch (floats)
#define STAGE_A (Bb*BKP)         // 5120 floats
#define STAGE_SZ (2*STAGE_A)     // A+B: 10240 floats
#define EPIP 132                 // epilogue smem pitch
#define GEMM_SMEM (2*STAGE_SZ*4) // 81920 bytes (>= 128*EPIP*4 = 67584)

__device__ __forceinline__ void cp_async16(float* dst, const float* src) {
    unsigned s = (unsigned)__cvta_generic_to_shared(dst);
    asm volatile("cp.async.cg.shared.global [%0], [%1], 16;\n" :: "r"(s), "l"(src));
}

template<int EPI>
__global__ __launch_bounds__(256) void gemm2(const float* __restrict__ A,
                                             const float* __restrict__ W,
                                             const float* __restrict__ bias,
                                             const float* __restrict__ res,
                                             float* __restrict__ C,
                                             int M, int N, int K)
{
    extern __shared__ float sm[];
    int tid  = threadIdx.x;
    int warp = tid >> 5;
    int wm   = warp >> 2;   // 0..1
    int wn   = warp & 3;    // 0..3
    int row0 = blockIdx.y * Bb;
    int col0 = blockIdx.x * Bn;

    wmma::fragment<wmma::accumulator, 16, 16, 8, float> acc[4][2];
    #pragma unroll
    for (int i = 0; i < 4; i++)
        #pragma unroll
        for (int j = 0; j < 2; j++)
            wmma::fill_fragment(acc[i][j], 0.0f);

    int ntiles = K / Bk;

    int lr[4], lc[4];
    #pragma unroll
    for (int j = 0; j < 4; j++) {
        int idx = tid + j * 256;
        lr[j] = idx >> 3;           // 0..127
        lc[j] = (idx & 7) << 2;     // 0,4,...,28
    }

    auto load_stage = [&](int s, int k0) {
        float* sA = sm + s * STAGE_SZ;
        float* sB = sA + STAGE_A;
        #pragma unroll
        for (int j = 0; j < 4; j++) {
            cp_async16(&sA[lr[j] * BKP + lc[j]], &A[(size_t)(row0 + lr[j]) * K + k0 + lc[j]]);
            cp_async16(&sB[lr[j] * BKP + lc[j]], &W[(size_t)(col0 + lr[j]) * K + k0 + lc[j]]);
        }
        asm volatile("cp.async.commit_group;\n" ::: "memory");
    };

    load_stage(0, 0);

    for (int t = 0; t < ntiles; t++) {
        if (t + 1 < ntiles) {
            load_stage((t + 1) & 1, (t + 1) * Bk);
            asm volatile("cp.async.wait_group 1;\n" ::: "memory");
        } else {
            asm volatile("cp.async.wait_group 0;\n" ::: "memory");
        }
        __syncthreads();

        float* sA = sm + (t & 1) * STAGE_SZ;
        float* sB = sA + STAGE_A;

        #pragma unroll
        for (int ks = 0; ks < Bk; ks += 8) {
            wmma::fragment<wmma::matrix_a, 16, 16, 8, wmma::precision::tf32, wmma::row_major> af[4];
            wmma::fragment<wmma::matrix_b, 16, 16, 8, wmma::precision::tf32, wmma::col_major> bf[2];
            #pragma unroll
            for (int i = 0; i < 4; i++)
                wmma::load_matrix_sync(af[i], &sA[(wm * 64 + i * 16) * BKP + ks], BKP);
            #pragma unroll
            for (int j = 0; j < 2; j++)
                wmma::load_matrix_sync(bf[j], &sB[(wn * 32 + j * 16) * BKP + ks], BKP);
            // operands pre-rounded to tf32: no per-element cvt needed
            #pragma unroll
            for (int i = 0; i < 4; i++)
                #pragma unroll
                for (int j = 0; j < 2; j++)
                    wmma::mma_sync(acc[i][j], af[i], bf[j], acc[i][j]);
        }
        __syncthreads();
    }

    // ---- fused epilogue through smem staging ----
    float* sC = sm;
    #pragma unroll
    for (int i = 0; i < 4; i++)
        #pragma unroll
        for (int j = 0; j < 2; j++)
            wmma::store_matrix_sync(&sC[(wm * 64 + i * 16) * EPIP + wn * 32 + j * 16],
                                    acc[i][j], EPIP, wmma::mem_row_major);
    __syncthreads();

    #pragma unroll
    for (int j = 0; j < 16; j++) {
        int idx = tid + j * 256;       // 4096 float4
        int r   = idx >> 5;            // 0..127
        int c4  = (idx & 31) << 2;     // 0..124
        float4 v = *(float4*)&sC[r * EPIP + c4];
        float4 b4 = *(const float4*)&bias[col0 + c4];
        v.x += b4.x; v.y += b4.y; v.z += b4.z; v.w += b4.w;
        if (EPI == 1) {
            float4 r4 = *(const float4*)&res[(size_t)(row0 + r) * N + col0 + c4];
            v.x += r4.x; v.y += r4.y; v.z += r4.z; v.w += r4.w;
        }
        if (EPI == 2) {
            v.x = tf32r(v.x * normcdff(v.x));
            v.y = tf32r(v.y * normcdff(v.y));
            v.z = tf32r(v.z * normcdff(v.z));
            v.w = tf32r(v.w * normcdff(v.w));
        }
        *(float4*)&C[(size_t)(row0 + r) * N + col0 + c4] = v;
    }
}

// =====================================================================
// FP32 flash attention v2, causal (output tf32-rounded -> feeds Wo GEMM).
// =====================================================================
#define FQP 68
#define FPP 76
#define OFF_Q 0
#define OFF_K (64*FQP)
#define OFF_V (OFF_K + 64*64)
#define OFF_P (OFF_V + 64*64)
#define FA_SMEM ((OFF_P + 64*FPP) * 4)

__global__ __launch_bounds__(128) void flash2(const float* __restrict__ Q,
                                              const float* __restrict__ K,
                                              const float* __restrict__ V,
                                              float* __restrict__ O)
{
    extern __shared__ float sm[];
    float* sQ = sm + OFF_Q;
    float* sK = sm + OFF_K;
    float* sV = sm + OFF_V;
    float* sP = sm + OFF_P;

    int qt = blockIdx.x, h = blockIdx.y, b = blockIdx.z;
    int q0 = qt * 64;
    int tid = threadIdx.x;
    int tx = tid & 7;
    int ty = tid >> 3;

    size_t baseQ = ((size_t)(b * SS + q0)) * EE + h * DD;
    #pragma unroll
    for (int j = 0; j < 8; j++) {
        int f = tid + j * 128;
        int row = f >> 4, c4 = (f & 15) << 2;
        float4 v = *(const float4*)&Q[baseQ + (size_t)row * EE + c4];
        v.x *= 0.125f; v.y *= 0.125f; v.z *= 0.125f; v.w *= 0.125f;
        *(float4*)&sQ[row * FQP + c4] = v;
    }

    float m[4], l[4], o[4][8];
    #pragma unroll
    for (int i = 0; i < 4; i++) {
        m[i] = -INFINITY; l[i] = 0.0f;
        #pragma unroll
        for (int d = 0; d < 8; d++) o[i][d] = 0.0f;
    }

    int nchunks = qt + 1;
    for (int ck = 0; ck < nchunks; ck++) {
        int c0 = ck * 64;
        __syncthreads();
        size_t baseK = ((size_t)(b * SS + c0)) * EE + h * DD;
        #pragma unroll
        for (int j = 0; j < 8; j++) {
            int f = tid + j * 128;
            int row = f >> 4, c16 = f & 15;
            int sw = (c16 ^ (row >> 3)) << 2;
            *(float4*)&sK[row * 64 + sw] = *(const float4*)&K[baseK + (size_t)row * EE + (c16 << 2)];
            *(float4*)&sV[row * 64 + sw] = *(const float4*)&V[baseK + (size_t)row * EE + (c16 << 2)];
        }
        __syncthreads();

        float acc[4][8];
        #pragma unroll
        for (int i = 0; i < 4; i++)
            #pragma unroll
            for (int j = 0; j < 8; j++) acc[i][j] = 0.0f;

        #pragma unroll 4
        for (int k = 0; k < 64; k += 4) {
            float4 q4[4];
            #pragma unroll
            for (int i = 0; i < 4; i++)
                q4[i] = *(const float4*)&sQ[(ty * 4 + i) * FQP + k];
            int kc = k >> 2;
            #pragma unroll
            for (int j = 0; j < 8; j++) {
                float4 k4 = *(const float4*)&sK[(tx * 8 + j) * 64 + ((kc ^ tx) << 2)];
                #pragma unroll
                for (int i = 0; i < 4; i++)
                    acc[i][j] += q4[i].x * k4.x + q4[i].y * k4.y + q4[i].z * k4.z + q4[i].w * k4.w;
            }
        }

        if (c0 == q0) {
            #pragma unroll
            for (int i = 0; i < 4; i++)
                #pragma unroll
                for (int j = 0; j < 8; j++)
                    if (tx * 8 + j > ty * 4 + i) acc[i][j] = -1.0e30f;
        }

        #pragma unroll
        for (int i = 0; i < 4; i++) {
            float mloc = acc[i][0];
            #pragma unroll
            for (int j = 1; j < 8; j++) mloc = fmaxf(mloc, acc[i][j]);
            mloc = fmaxf(mloc, __shfl_xor_sync(0xffffffffu, mloc, 1));
            mloc = fmaxf(mloc, __shfl_xor_sync(0xffffffffu, mloc, 2));
            mloc = fmaxf(mloc, __shfl_xor_sync(0xffffffffu, mloc, 4));
            float mnew  = fmaxf(m[i], mloc);
            float alpha = __expf(m[i] - mnew);
            float ssum = 0.0f;
            #pragma unroll
            for (int j = 0; j < 8; j++) {
                float p = __expf(acc[i][j] - mnew);
                acc[i][j] = p;
                ssum += p;
            }
            ssum += __shfl_xor_sync(0xffffffffu, ssum, 1);
            ssum += __shfl_xor_sync(0xffffffffu, ssum, 2);
            ssum += __shfl_xor_sync(0xffffffffu, ssum, 4);
            l[i] = l[i] * alpha + ssum;
            m[i] = mnew;
            #pragma unroll
            for (int d = 0; d < 8; d++) o[i][d] *= alpha;
            float4 p0 = make_float4(acc[i][0], acc[i][1], acc[i][2], acc[i][3]);
            float4 p1 = make_float4(acc[i][4], acc[i][5], acc[i][6], acc[i][7]);
            *(float4*)&sP[(ty * 4 + i) * FPP + tx * 8]     = p0;
            *(float4*)&sP[(ty * 4 + i) * FPP + tx * 8 + 4] = p1;
        }
        __syncwarp();

        #pragma unroll 4
        for (int cc = 0; cc < 64; cc += 4) {
            float4 p[4];
            #pragma unroll
            for (int i = 0; i < 4; i++)
                p[i] = *(const float4*)&sP[(ty * 4 + i) * FPP + cc];
            #pragma unroll
            for (int j2 = 0; j2 < 4; j2++) {
                int c = cc + j2;
                int s = c >> 3;
                float4 v0 = *(const float4*)&sV[c * 64 + (((tx * 2)     ^ s) << 2)];
                float4 v1 = *(const float4*)&sV[c * 64 + (((tx * 2 + 1) ^ s) << 2)];
                #pragma unroll
                for (int i = 0; i < 4; i++) {
                    float pv = ((const float*)&p[i])[j2];
                    o[i][0] += pv * v0.x; o[i][1] += pv * v0.y;
                    o[i][2] += pv * v0.z; o[i][3] += pv * v0.w;
                    o[i][4] += pv * v1.x; o[i][5] += pv * v1.y;
                    o[i][6] += pv * v1.z; o[i][7] += pv * v1.w;
                }
            }
        }
    }

    #pragma unroll
    for (int i = 0; i < 4; i++) {
        float inv = 1.0f / l[i];
        size_t baseO = ((size_t)(b * SS + q0 + ty * 4 + i)) * EE + h * DD + tx * 8;
        float4 v0, v1;
        v0.x = tf32r(o[i][0] * inv); v0.y = tf32r(o[i][1] * inv);
        v0.z = tf32r(o[i][2] * inv); v0.w = tf32r(o[i][3] * inv);
        v1.x = tf32r(o[i][4] * inv); v1.y = tf32r(o[i][5] * inv);
        v1.z = tf32r(o[i][6] * inv); v1.w = tf32r(o[i][7] * inv);
        *(float4*)&O[baseO]     = v0;
        *(float4*)&O[baseO + 4] = v1;
    }
}

// ---------------- launch ----------------
extern "C" void kernel_launch(void* const* d_in, const int* in_sizes, int n_in,
                              void* d_out, int out_size)
{
    (void)in_sizes; (void)n_in; (void)out_size;
    const float* x     = (const float*)d_in[0];
    const float* ln1_g = (const float*)d_in[2];
    const float* ln1_b = (const float*)d_in[3];
    const float* Wq    = (const float*)d_in[4];
    const float* bq    = (const float*)d_in[5];
    const float* Wk    = (const float*)d_in[6];
    const float* bk    = (const float*)d_in[7];
    const float* Wv    = (const float*)d_in[8];
    const float* bv    = (const float*)d_in[9];
    const float* Wo    = (const float*)d_in[10];
    const float* bo    = (const float*)d_in[11];
    const float* ln2_g = (const float*)d_in[12];
    const float* ln2_b = (const float*)d_in[13];
    const float* W1    = (const float*)d_in[14];
    const float* b1    = (const float*)d_in[15];
    const float* W2    = (const float*)d_in[16];
    const float* b2    = (const float*)d_in[17];
    float* out = (float*)d_out;

    void* p;
    float *ln, *q, *k, *v, *ctx, *x1, *mid, *wr;
    cudaGetSymbolAddress(&p, g_ln);  ln  = (float*)p;
    cudaGetSymbolAddress(&p, g_q);   q   = (float*)p;
    cudaGetSymbolAddress(&p, g_k);   k   = (float*)p;
    cudaGetSymbolAddress(&p, g_v);   v   = (float*)p;
    cudaGetSymbolAddress(&p, g_ctx); ctx = (float*)p;
    cudaGetSymbolAddress(&p, g_x1);  x1  = (float*)p;
    cudaGetSymbolAddress(&p, g_mid); mid = (float*)p;
    cudaGetSymbolAddress(&p, g_wr);  wr  = (float*)p;

    const int M1 = 1024 * 1024;
    float* wq2 = wr;
    float* wk2 = wr + 1 * M1;
    float* wv2 = wr + 2 * M1;
    float* wo2 = wr + 3 * M1;
    float* w12 = wr + 4 * M1;   // 4M floats
    float* w22 = wr + 8 * M1;   // 4M floats

    cudaFuncSetAttribute(gemm2<0>, cudaFuncAttributeMaxDynamicSharedMemorySize, GEMM_SMEM);
    cudaFuncSetAttribute(gemm2<1>, cudaFuncAttributeMaxDynamicSharedMemorySize, GEMM_SMEM);
    cudaFuncSetAttribute(gemm2<2>, cudaFuncAttributeMaxDynamicSharedMemorySize, GEMM_SMEM);
    cudaFuncSetAttribute(flash2,   cudaFuncAttributeMaxDynamicSharedMemorySize, FA_SMEM);

    dim3 gE(EE / Bn, MM / Bb);   // (8, 64)
    dim3 gF(FF / Bn, MM / Bb);   // (32, 64)

    // 0) pre-round weights to tf32
    round_kernel<<<512, 256>>>(Wq, wq2, M1 / 4);
    round_kernel<<<512, 256>>>(Wk, wk2, M1 / 4);
    round_kernel<<<512, 256>>>(Wv, wv2, M1 / 4);
    round_kernel<<<512, 256>>>(Wo, wo2, M1 / 4);
    round_kernel<<<1024, 256>>>(W1, w12, 4 * M1 / 4);
    round_kernel<<<1024, 256>>>(W2, w22, 4 * M1 / 4);

    // 1) ln1 (tf32-rounded output)
    ln_kernel<<<MM, 256>>>(x, ln1_g, ln1_b, ln);
    // 2) QKV projections (+bias fused)
    gemm2<0><<<gE, 256, GEMM_SMEM>>>(ln, wq2, bq, nullptr, q, MM, EE, EE);
    gemm2<0><<<gE, 256, GEMM_SMEM>>>(ln, wk2, bk, nullptr, k, MM, EE, EE);
    gemm2<0><<<gE, 256, GEMM_SMEM>>>(ln, wv2, bv, nullptr, v, MM, EE, EE);
    // 3) attention (ctx tf32-rounded)
    flash2<<<dim3(SS / 64, HH, BB), 128, FA_SMEM>>>(q, k, v, ctx);
    // 4) output projection + bias + residual -> x1
    gemm2<1><<<gE, 256, GEMM_SMEM>>>(ctx, wo2, bo, x, x1, MM, EE, EE);
    // 5) ln2 (tf32-rounded output)
    ln_kernel<<<MM, 256>>>(x1, ln2_g, ln2_b, ln);
    // 6) FFN: W1 + bias + gelu fused (tf32-rounded), then W2 + bias + residual
    gemm2<2><<<gF, 256, GEMM_SMEM>>>(ln, w12, b1, nullptr, mid, MM, FF, EE);
    gemm2<1><<<gE, 256, GEMM_SMEM>>>(mid, w22, b2, x1, out, MM, EE, FF);
}

// round 13
// speedup vs baseline: 2.2359x; 2.2359x over previous
#include <cuda_runtime.h>
#include <cuda_fp16.h>
#include <mma.h>
#include <math.h>
#include <cstdint>
#include <cstddef>

using namespace nvcuda;

// Problem dims
#define BB 4
#define SS 2048
#define EE 1024
#define HH 16
#define DD 64
#define FF 4096
#define MM (BB*SS)   // 8192 tokens

// ---------------- scratch (no allocations allowed) ----------------
__device__ __half g_lnh [MM*EE];            // LN outputs (half, GEMM A operand)
__device__ float  g_q   [MM*EE];
__device__ float  g_k   [MM*EE];
__device__ float  g_v   [MM*EE];
__device__ __half g_ctxh[MM*EE];            // attention output (half)
__device__ float  g_x1  [MM*EE];
__device__ __half g_midh[(size_t)MM*FF];    // FFN mid (half)
__device__ __half g_wh  [12*1024*1024];     // half weights: Wq,Wk,Wv,Wo,W1,W2

// ---------------- fp32 -> fp16 weight conversion ----------------
__global__ void cvt_kernel(const float* __restrict__ src, __half* __restrict__ dst, int n4)
{
    int stride = gridDim.x * blockDim.x;
    for (int i = blockIdx.x * blockDim.x + threadIdx.x; i < n4; i += stride) {
        float4 v = ((const float4*)src)[i];
        __align__(8) __half2 t[2];
        t[0] = __floats2half2_rn(v.x, v.y);
        t[1] = __floats2half2_rn(v.z, v.w);
        ((uint2*)dst)[i] = *(uint2*)t;
    }
}

// ---------------- LayerNorm: one block per row of 1024; half output ----------------
__global__ __launch_bounds__(256) void ln_kernel(const float* __restrict__ x,
                                                 const float* __restrict__ g,
                                                 const float* __restrict__ b,
                                                 __half* __restrict__ y)
{
    int row = blockIdx.x;
    int tid = threadIdx.x;
    const float4* xr = (const float4*)(x + (size_t)row * EE);
    float4 v = xr[tid];
    float s  = v.x + v.y + v.z + v.w;
    float ss = v.x*v.x + v.y*v.y + v.z*v.z + v.w*v.w;

    __shared__ float rs[8], rss[8];
    #pragma unroll
    for (int o = 16; o > 0; o >>= 1) {
        s  += __shfl_down_sync(0xffffffffu, s,  o);
        ss += __shfl_down_sync(0xffffffffu, ss, o);
    }
    int w = tid >> 5;
    if ((tid & 31) == 0) { rs[w] = s; rss[w] = ss; }
    __syncthreads();
    __shared__ float sh_mean, sh_rstd;
    if (tid == 0) {
        float S1 = 0.f, S2 = 0.f;
        #pragma unroll
        for (int i = 0; i < 8; i++) { S1 += rs[i]; S2 += rss[i]; }
        float mean = S1 * (1.0f / EE);
        float var  = S2 * (1.0f / EE) - mean * mean;
        sh_mean = mean;
        sh_rstd = rsqrtf(var + 1e-5f);
    }
    __syncthreads();
    float mean = sh_mean, rstd = sh_rstd;
    float4 g4 = ((const float4*)g)[tid];
    float4 b4 = ((const float4*)b)[tid];
    float ox = (v.x - mean) * rstd * g4.x + b4.x;
    float oy = (v.y - mean) * rstd * g4.y + b4.y;
    float oz = (v.z - mean) * rstd * g4.z + b4.z;
    float ow = (v.w - mean) * rstd * g4.w + b4.w;
    __align__(8) __half2 t[2];
    t[0] = __floats2half2_rn(ox, oy);
    t[1] = __floats2half2_rn(oz, ow);
    ((uint2*)(y + (size_t)row * EE))[tid] = *(uint2*)t;
}

// =====================================================================
// FP16 GEMM (fp32 accum): C[M,N] = A[M,K] @ W[N,K]^T  (+ fused epilogue)
// 128x128 block, BK=32 halves, 3-stage cp.async ring, 256 threads,
// 8 warps x (64x32) via wmma 16x16x16 half (LDSM path).
// EPI: 0 = +bias -> float   1 = +bias +res -> float   2 = gelu(+bias) -> half
// =====================================================================
#define HP 40                    // smem pitch in halves (80B: conflict-free ldsm)
#define HTILE (128*HP)           // halves per operand tile (5120)
#define HSTAGE (2*HTILE)         // A+B per stage (10240 halves = 20480 B)
#define EPIP 132                 // epilogue float pitch
#define GH_SMEM (128*EPIP*4)     // 67584 B (> 3*HSTAGE*2 = 61440 B)

__device__ __forceinline__ void cp_async16h(__half* dst, const __half* src) {
    unsigned s = (unsigned)__cvta_generic_to_shared(dst);
    asm volatile("cp.async.cg.shared.global [%0], [%1], 16;\n" :: "r"(s), "l"(src));
}

template<int EPI>
__global__ __launch_bounds__(256, 2) void gemmh(const __half* __restrict__ A,
                                                const __half* __restrict__ W,
                                                const float* __restrict__ bias,
                                                const float* __restrict__ res,
                                                void* __restrict__ Cv,
                                                int M, int N, int K)
{
    extern __shared__ float dsmf[];
    __half* dsmh = (__half*)dsmf;

    int tid  = threadIdx.x;
    int warp = tid >> 5;
    int wm   = warp >> 2;   // 0..1 (M dir, 64 rows)
    int wn   = warp & 3;    // 0..3 (N dir, 32 cols)
    int row0 = blockIdx.y * 128;
    int col0 = blockIdx.x * 128;

    wmma::fragment<wmma::accumulator, 16, 16, 16, float> acc[4][2];
    #pragma unroll
    for (int i = 0; i < 4; i++)
        #pragma unroll
        for (int j = 0; j < 2; j++)
            wmma::fill_fragment(acc[i][j], 0.0f);

    const int T = K / 32;

    auto load_stage = [&](int t) {
        int s = t % 3;
        __half* sA = dsmh + s * HSTAGE;
        __half* sB = sA + HTILE;
        const __half* Ag = A + (size_t)row0 * K + t * 32;
        const __half* Wg = W + (size_t)col0 * K + t * 32;
        #pragma unroll
        for (int j = 0; j < 2; j++) {
            int idx = tid + j * 256;
            int r   = idx >> 2;         // 0..127
            int c8  = (idx & 3) << 3;   // 0,8,16,24 halves
            cp_async16h(&sA[r * HP + c8], &Ag[(size_t)r * K + c8]);
            cp_async16h(&sB[r * HP + c8], &Wg[(size_t)r * K + c8]);
        }
        asm volatile("cp.async.commit_group;\n" ::: "memory");
    };

    load_stage(0);
    load_stage(1);

    for (int t = 0; t < T; t++) {
        if (t + 1 < T) {
            asm volatile("cp.async.wait_group 1;\n" ::: "memory");
        } else {
            asm volatile("cp.async.wait_group 0;\n" ::: "memory");
        }
        __syncthreads();
        if (t + 2 < T) load_stage(t + 2);

        __half* sA = dsmh + (t % 3) * HSTAGE;
        __half* sB = sA + HTILE;

        #pragma unroll
        for (int ks = 0; ks < 2; ks++) {
            wmma::fragment<wmma::matrix_a, 16, 16, 16, __half, wmma::row_major> af[4];
            wmma::fragment<wmma::matrix_b, 16, 16, 16, __half, wmma::col_major> bf[2];
            #pragma unroll
            for (int i = 0; i < 4; i++)
                wmma::load_matrix_sync(af[i], &sA[(wm * 64 + i * 16) * HP + ks * 16], HP);
            #pragma unroll
            for (int j = 0; j < 2; j++)
                wmma::load_matrix_sync(bf[j], &sB[(wn * 32 + j * 16) * HP + ks * 16], HP);
            #pragma unroll
            for (int i = 0; i < 4; i++)
                #pragma unroll
                for (int j = 0; j < 2; j++)
                    wmma::mma_sync(acc[i][j], af[i], bf[j], acc[i][j]);
        }
    }
    __syncthreads();   // protect smem reuse by epilogue staging

    // ---- fused epilogue through smem staging ----
    float* sC = dsmf;
    #pragma unroll
    for (int i = 0; i < 4; i++)
        #pragma unroll
        for (int j = 0; j < 2; j++)
            wmma::store_matrix_sync(&sC[(wm * 64 + i * 16) * EPIP + wn * 32 + j * 16],
                                    acc[i][j], EPIP, wmma::mem_row_major);
    __syncthreads();

    #pragma unroll
    for (int j = 0; j < 16; j++) {
        int idx = tid + j * 256;       // 4096 float4
        int r   = idx >> 5;            // 0..127
        int c4  = (idx & 31) << 2;     // 0..124
        float4 v = *(float4*)&sC[r * EPIP + c4];
        float4 b4 = *(const float4*)&bias[col0 + c4];
        v.x += b4.x; v.y += b4.y; v.z += b4.z; v.w += b4.w;
        if (EPI == 1) {
            float4 r4 = *(const float4*)&res[(size_t)(row0 + r) * N + col0 + c4];
            v.x += r4.x; v.y += r4.y; v.z += r4.z; v.w += r4.w;
            *(float4*)&((float*)Cv)[(size_t)(row0 + r) * N + col0 + c4] = v;
        } else if (EPI == 2) {
            v.x = v.x * normcdff(v.x);
            v.y = v.y * normcdff(v.y);
            v.z = v.z * normcdff(v.z);
            v.w = v.w * normcdff(v.w);
            __align__(8) __half2 t2[2];
            t2[0] = __floats2half2_rn(v.x, v.y);
            t2[1] = __floats2half2_rn(v.z, v.w);
            *(uint2*)&((__half*)Cv)[(size_t)(row0 + r) * N + col0 + c4] = *(uint2*)t2;
        } else {
            *(float4*)&((float*)Cv)[(size_t)(row0 + r) * N + col0 + c4] = v;
        }
    }
}

// =====================================================================
// FP32 flash attention, causal (half output feeding the Wo GEMM).
// =====================================================================
#define FQP 68
#define FPP 76
#define OFF_Q 0
#define OFF_K (64*FQP)
#define OFF_V (OFF_K + 64*64)
#define OFF_P (OFF_V + 64*64)
#define FA_SMEM ((OFF_P + 64*FPP) * 4)

__global__ __launch_bounds__(128) void flash2(const float* __restrict__ Q,
                                              const float* __restrict__ K,
                                              const float* __restrict__ V,
                                              __half* __restrict__ O)
{
    extern __shared__ float sm[];
    float* sQ = sm + OFF_Q;
    float* sK = sm + OFF_K;
    float* sV = sm + OFF_V;
    float* sP = sm + OFF_P;

    int qt = blockIdx.x, h = blockIdx.y, b = blockIdx.z;
    int q0 = qt * 64;
    int tid = threadIdx.x;
    int tx = tid & 7;
    int ty = tid >> 3;

    size_t baseQ = ((size_t)(b * SS + q0)) * EE + h * DD;
    #pragma unroll
    for (int j = 0; j < 8; j++) {
        int f = tid + j * 128;
        int row = f >> 4, c4 = (f & 15) << 2;
        float4 v = *(const float4*)&Q[baseQ + (size_t)row * EE + c4];
        v.x *= 0.125f; v.y *= 0.125f; v.z *= 0.125f; v.w *= 0.125f;
        *(float4*)&sQ[row * FQP + c4] = v;
    }

    float m[4], l[4], o[4][8];
    #pragma unroll
    for (int i = 0; i < 4; i++) {
        m[i] = -INFINITY; l[i] = 0.0f;
        #pragma unroll
        for (int d = 0; d < 8; d++) o[i][d] = 0.0f;
    }

    int nchunks = qt + 1;
    for (int ck = 0; ck < nchunks; ck++) {
        int c0 = ck * 64;
        __syncthreads();
        size_t baseK = ((size_t)(b * SS + c0)) * EE + h * DD;
        #pragma unroll
        for (int j = 0; j < 8; j++) {
            int f = tid + j * 128;
            int row = f >> 4, c16 = f & 15;
            int sw = (c16 ^ (row >> 3)) << 2;
            *(float4*)&sK[row * 64 + sw] = *(const float4*)&K[baseK + (size_t)row * EE + (c16 << 2)];
            *(float4*)&sV[row * 64 + sw] = *(const float4*)&V[baseK + (size_t)row * EE + (c16 << 2)];
        }
        __syncthreads();

        float acc[4][8];
        #pragma unroll
        for (int i = 0; i < 4; i++)
            #pragma unroll
            for (int j = 0; j < 8; j++) acc[i][j] = 0.0f;

        #pragma unroll 4
        for (int k = 0; k < 64; k += 4) {
            float4 q4[4];
            #pragma unroll
            for (int i = 0; i < 4; i++)
                q4[i] = *(const float4*)&sQ[(ty * 4 + i) * FQP + k];
            int kc = k >> 2;
            #pragma unroll
            for (int j = 0; j < 8; j++) {
                float4 k4 = *(const float4*)&sK[(tx * 8 + j) * 64 + ((kc ^ tx) << 2)];
                #pragma unroll
                for (int i = 0; i < 4; i++)
                    acc[i][j] += q4[i].x * k4.x + q4[i].y * k4.y + q4[i].z * k4.z + q4[i].w * k4.w;
            }
        }

        if (c0 == q0) {
            #pragma unroll
            for (int i = 0; i < 4; i++)
                #pragma unroll
                for (int j = 0; j < 8; j++)
                    if (tx * 8 + j > ty * 4 + i) acc[i][j] = -1.0e30f;
        }

        #pragma unroll
        for (int i = 0; i < 4; i++) {
            float mloc = acc[i][0];
            #pragma unroll
            for (int j = 1; j < 8; j++) mloc = fmaxf(mloc, acc[i][j]);
            mloc = fmaxf(mloc, __shfl_xor_sync(0xffffffffu, mloc, 1));
            mloc = fmaxf(mloc, __shfl_xor_sync(0xffffffffu, mloc, 2));
            mloc = fmaxf(mloc, __shfl_xor_sync(0xffffffffu, mloc, 4));
            float mnew  = fmaxf(m[i], mloc);
            float alpha = __expf(m[i] - mnew);
            float ssum = 0.0f;
            #pragma unroll
            for (int j = 0; j < 8; j++) {
                float p = __expf(acc[i][j] - mnew);
                acc[i][j] = p;
                ssum += p;
            }
            ssum += __shfl_xor_sync(0xffffffffu, ssum, 1);
            ssum += __shfl_xor_sync(0xffffffffu, ssum, 2);
            ssum += __shfl_xor_sync(0xffffffffu, ssum, 4);
            l[i] = l[i] * alpha + ssum;
            m[i] = mnew;
            #pragma unroll
            for (int d = 0; d < 8; d++) o[i][d] *= alpha;
            float4 p0 = make_float4(acc[i][0], acc[i][1], acc[i][2], acc[i][3]);
            float4 p1 = make_float4(acc[i][4], acc[i][5], acc[i][6], acc[i][7]);
            *(float4*)&sP[(ty * 4 + i) * FPP + tx * 8]     = p0;
            *(float4*)&sP[(ty * 4 + i) * FPP + tx * 8 + 4] = p1;
        }
        __syncwarp();

        #pragma unroll 4
        for (int cc = 0; cc < 64; cc += 4) {
            float4 p[4];
            #pragma unroll
            for (int i = 0; i < 4; i++)
                p[i] = *(const float4*)&sP[(ty * 4 + i) * FPP + cc];
            #pragma unroll
            for (int j2 = 0; j2 < 4; j2++) {
                int c = cc + j2;
                int s = c >> 3;
                float4 v0 = *(const float4*)&sV[c * 64 + (((tx * 2)     ^ s) << 2)];
                float4 v1 = *(const float4*)&sV[c * 64 + (((tx * 2 + 1) ^ s) << 2)];
                #pragma unroll
                for (int i = 0; i < 4; i++) {
                    float pv = ((const float*)&p[i])[j2];
                    o[i][0] += pv * v0.x; o[i][1] += pv * v0.y;
                    o[i][2] += pv * v0.z; o[i][3] += pv * v0.w;
                    o[i][4] += pv * v1.x; o[i][5] += pv * v1.y;
                    o[i][6] += pv * v1.z; o[i][7] += pv * v1.w;
                }
            }
        }
    }

    #pragma unroll
    for (int i = 0; i < 4; i++) {
        float inv = 1.0f / l[i];
        size_t baseO = ((size_t)(b * SS + q0 + ty * 4 + i)) * EE + h * DD + tx * 8;
        __align__(16) __half2 t2[4];
        t2[0] = __floats2half2_rn(o[i][0] * inv, o[i][1] * inv);
        t2[1] = __floats2half2_rn(o[i][2] * inv, o[i][3] * inv);
        t2[2] = __floats2half2_rn(o[i][4] * inv, o[i][5] * inv);
        t2[3] = __floats2half2_rn(o[i][6] * inv, o[i][7] * inv);
        *(uint4*)&O[baseO] = *(uint4*)t2;
    }
}

// ---------------- launch ----------------
extern "C" void kernel_launch(void* const* d_in, const int* in_sizes, int n_in,
                              void* d_out, int out_size)
{
    (void)in_sizes; (void)n_in; (void)out_size;
    const float* x     = (const float*)d_in[0];
    const float* ln1_g = (const float*)d_in[2];
    const float* ln1_b = (const float*)d_in[3];
    const float* Wq    = (const float*)d_in[4];
    const float* bq    = (const float*)d_in[5];
    const float* Wk    = (const float*)d_in[6];
    const float* bk    = (const float*)d_in[7];
    const float* Wv    = (const float*)d_in[8];
    const float* bv    = (const float*)d_in[9];
    const float* Wo    = (const float*)d_in[10];
    const float* bo    = (const float*)d_in[11];
    const float* ln2_g = (const float*)d_in[12];
    const float* ln2_b = (const float*)d_in[13];
    const float* W1    = (const float*)d_in[14];
    const float* b1    = (const float*)d_in[15];
    const float* W2    = (const float*)d_in[16];
    const float* b2    = (const float*)d_in[17];
    float* out = (float*)d_out;

    void* p;
    __half *lnh, *ctxh, *midh, *wh;
    float *q, *k, *v, *x1;
    cudaGetSymbolAddress(&p, g_lnh);  lnh  = (__half*)p;
    cudaGetSymbolAddress(&p, g_q);    q    = (float*)p;
    cudaGetSymbolAddress(&p, g_k);    k    = (float*)p;
    cudaGetSymbolAddress(&p, g_v);    v    = (float*)p;
    cudaGetSymbolAddress(&p, g_ctxh); ctxh = (__half*)p;
    cudaGetSymbolAddress(&p, g_x1);   x1   = (float*)p;
    cudaGetSymbolAddress(&p, g_midh); midh = (__half*)p;
    cudaGetSymbolAddress(&p, g_wh);   wh   = (__half*)p;

    const int M1 = 1024 * 1024;
    __half* wq2 = wh;
    __half* wk2 = wh + 1 * M1;
    __half* wv2 = wh + 2 * M1;
    __half* wo2 = wh + 3 * M1;
    __half* w12 = wh + 4 * M1;   // 4M halves
    __half* w22 = wh + 8 * M1;   // 4M halves

    cudaFuncSetAttribute(gemmh<0>, cudaFuncAttributeMaxDynamicSharedMemorySize, GH_SMEM);
    cudaFuncSetAttribute(gemmh<1>, cudaFuncAttributeMaxDynamicSharedMemorySize, GH_SMEM);
    cudaFuncSetAttribute(gemmh<2>, cudaFuncAttributeMaxDynamicSharedMemorySize, GH_SMEM);
    cudaFuncSetAttribute(flash2,   cudaFuncAttributeMaxDynamicSharedMemorySize, FA_SMEM);

    dim3 gE(EE / 128, MM / 128);   // (8, 64)
    dim3 gF(FF / 128, MM / 128);   // (32, 64)

    // 0) convert weights to fp16 once per replay
    cvt_kernel<<<512, 256>>>(Wq, wq2, M1 / 4);
    cvt_kernel<<<512, 256>>>(Wk, wk2, M1 / 4);
    cvt_kernel<<<512, 256>>>(Wv, wv2, M1 / 4);
    cvt_kernel<<<512, 256>>>(Wo, wo2, M1 / 4);
    cvt_kernel<<<1024, 256>>>(W1, w12, M1);
    cvt_kernel<<<1024, 256>>>(W2, w22, M1);

    // 1) ln1 (half out)
    ln_kernel<<<MM, 256>>>(x, ln1_g, ln1_b, lnh);
    // 2) QKV projections (+bias fused, fp32 out)
    gemmh<0><<<gE, 256, GH_SMEM>>>(lnh, wq2, bq, nullptr, q, MM, EE, EE);
    gemmh<0><<<gE, 256, GH_SMEM>>>(lnh, wk2, bk, nullptr, k, MM, EE, EE);
    gemmh<0><<<gE, 256, GH_SMEM>>>(lnh, wv2, bv, nullptr, v, MM, EE, EE);
    // 3) attention (half ctx out)
    flash2<<<dim3(SS / 64, HH, BB), 128, FA_SMEM>>>(q, k, v, ctxh);
    // 4) output projection + bias + residual -> x1 (fp32)
    gemmh<1><<<gE, 256, GH_SMEM>>>(ctxh, wo2, bo, x, x1, MM, EE, EE);
    // 5) ln2 (half out)
    ln_kernel<<<MM, 256>>>(x1, ln2_g, ln2_b, lnh);
    // 6) FFN: W1 + bias + gelu (half out), then W2 + bias + residual (fp32 out)
    gemmh<2><<<gF, 256, GH_SMEM>>>(lnh, w12, b1, nullptr, midh, MM, FF, EE);
    gemmh<1><<<gE, 256, GH_SMEM>>>(midh, w22, b2, x1, out, MM, EE, FF);
}

// round 14
// speedup vs baseline: 2.8998x; 1.2969x over previous
#include <cuda_runtime.h>
#include <cuda_fp16.h>
#include <mma.h>
#include <math.h>
#include <cstdint>
#include <cstddef>

using namespace nvcuda;

// Problem dims
#define BB 4
#define SS 2048
#define EE 1024
#define HH 16
#define DD 64
#define FF 4096
#define MM (BB*SS)   // 8192 tokens

// ---------------- scratch (no allocations allowed) ----------------
__device__ __half g_lnh [MM*EE];
__device__ __half g_qh  [MM*EE];
__device__ __half g_kh  [MM*EE];
__device__ __half g_vh  [MM*EE];
__device__ __half g_ctxh[MM*EE];
__device__ float  g_x1  [MM*EE];
__device__ __half g_midh[(size_t)MM*FF];
__device__ __half g_wh  [12*1024*1024];

__device__ __forceinline__ unsigned su32(const void* p) {
    return (unsigned)__cvta_generic_to_shared(p);
}
__device__ __forceinline__ unsigned h2pack(float a, float b) {
    __half2 t = __floats2half2_rn(a, b);
    return *(unsigned*)&t;
}

// ---------------- fp32 -> fp16 weight conversion ----------------
__global__ void cvt_kernel(const float* __restrict__ src, __half* __restrict__ dst, int n4)
{
    int stride = gridDim.x * blockDim.x;
    for (int i = blockIdx.x * blockDim.x + threadIdx.x; i < n4; i += stride) {
        float4 v = ((const float4*)src)[i];
        __align__(8) __half2 t[2];
        t[0] = __floats2half2_rn(v.x, v.y);
        t[1] = __floats2half2_rn(v.z, v.w);
        ((uint2*)dst)[i] = *(uint2*)t;
    }
}

// ---------------- LayerNorm: one block per row of 1024; half output ----------------
__global__ __launch_bounds__(256) void ln_kernel(const float* __restrict__ x,
                                                 const float* __restrict__ g,
                                                 const float* __restrict__ b,
                                                 __half* __restrict__ y)
{
    int row = blockIdx.x;
    int tid = threadIdx.x;
    const float4* xr = (const float4*)(x + (size_t)row * EE);
    float4 v = xr[tid];
    float s  = v.x + v.y + v.z + v.w;
    float ss = v.x*v.x + v.y*v.y + v.z*v.z + v.w*v.w;

    __shared__ float rs[8], rss[8];
    #pragma unroll
    for (int o = 16; o > 0; o >>= 1) {
        s  += __shfl_down_sync(0xffffffffu, s,  o);
        ss += __shfl_down_sync(0xffffffffu, ss, o);
    }
    int w = tid >> 5;
    if ((tid & 31) == 0) { rs[w] = s; rss[w] = ss; }
    __syncthreads();
    __shared__ float sh_mean, sh_rstd;
    if (tid == 0) {
        float S1 = 0.f, S2 = 0.f;
        #pragma unroll
        for (int i = 0; i < 8; i++) { S1 += rs[i]; S2 += rss[i]; }
        float mean = S1 * (1.0f / EE);
        float var  = S2 * (1.0f / EE) - mean * mean;
        sh_mean = mean;
        sh_rstd = rsqrtf(var + 1e-5f);
    }
    __syncthreads();
    float mean = sh_mean, rstd = sh_rstd;
    float4 g4 = ((const float4*)g)[tid];
    float4 b4 = ((const float4*)b)[tid];
    float ox = (v.x - mean) * rstd * g4.x + b4.x;
    float oy = (v.y - mean) * rstd * g4.y + b4.y;
    float oz = (v.z - mean) * rstd * g4.z + b4.z;
    float ow = (v.w - mean) * rstd * g4.w + b4.w;
    __align__(8) __half2 t[2];
    t[0] = __floats2half2_rn(ox, oy);
    t[1] = __floats2half2_rn(oz, ow);
    ((uint2*)(y + (size_t)row * EE))[tid] = *(uint2*)t;
}

// =====================================================================
// FP16 GEMM (fp32 accum): C[M,N] = A[M,K] @ W[N,K]^T  (+ fused epilogue)
// EPI: 0 = (acc+bias)*oscale -> half   1 = acc+bias+res -> float
//      2 = gelu(acc+bias) -> half
// =====================================================================
#define HP 40
#define HTILE (128*HP)
#define HSTAGE (2*HTILE)
#define EPIP 132
#define GH_SMEM (128*EPIP*4)

__device__ __forceinline__ void cp_async16h(__half* dst, const __half* src) {
    unsigned s = (unsigned)__cvta_generic_to_shared(dst);
    asm volatile("cp.async.cg.shared.global [%0], [%1], 16;\n" :: "r"(s), "l"(src));
}

template<int EPI>
__global__ __launch_bounds__(256, 2) void gemmh(const __half* __restrict__ A,
                                                const __half* __restrict__ W,
                                                const float* __restrict__ bias,
                                                const float* __restrict__ res,
                                                void* __restrict__ Cv,
                                                int M, int N, int K, float oscale)
{
    extern __shared__ float dsmf[];
    __half* dsmh = (__half*)dsmf;

    int tid  = threadIdx.x;
    int warp = tid >> 5;
    int wm   = warp >> 2;
    int wn   = warp & 3;
    int row0 = blockIdx.y * 128;
    int col0 = blockIdx.x * 128;

    wmma::fragment<wmma::accumulator, 16, 16, 16, float> acc[4][2];
    #pragma unroll
    for (int i = 0; i < 4; i++)
        #pragma unroll
        for (int j = 0; j < 2; j++)
            wmma::fill_fragment(acc[i][j], 0.0f);

    const int T = K / 32;

    auto load_stage = [&](int t) {
        int s = t % 3;
        __half* sA = dsmh + s * HSTAGE;
        __half* sB = sA + HTILE;
        const __half* Ag = A + (size_t)row0 * K + t * 32;
        const __half* Wg = W + (size_t)col0 * K + t * 32;
        #pragma unroll
        for (int j = 0; j < 2; j++) {
            int idx = tid + j * 256;
            int r   = idx >> 2;
            int c8  = (idx & 3) << 3;
            cp_async16h(&sA[r * HP + c8], &Ag[(size_t)r * K + c8]);
            cp_async16h(&sB[r * HP + c8], &Wg[(size_t)r * K + c8]);
        }
        asm volatile("cp.async.commit_group;\n" ::: "memory");
    };

    load_stage(0);
    load_stage(1);

    for (int t = 0; t < T; t++) {
        if (t + 1 < T) {
            asm volatile("cp.async.wait_group 1;\n" ::: "memory");
        } else {
            asm volatile("cp.async.wait_group 0;\n" ::: "memory");
        }
        __syncthreads();
        if (t + 2 < T) load_stage(t + 2);

        __half* sA = dsmh + (t % 3) * HSTAGE;
        __half* sB = sA + HTILE;

        #pragma unroll
        for (int ks = 0; ks < 2; ks++) {
            wmma::fragment<wmma::matrix_a, 16, 16, 16, __half, wmma::row_major> af[4];
            wmma::fragment<wmma::matrix_b, 16, 16, 16, __half, wmma::col_major> bf[2];
            #pragma unroll
            for (int i = 0; i < 4; i++)
                wmma::load_matrix_sync(af[i], &sA[(wm * 64 + i * 16) * HP + ks * 16], HP);
            #pragma unroll
            for (int j = 0; j < 2; j++)
                wmma::load_matrix_sync(bf[j], &sB[(wn * 32 + j * 16) * HP + ks * 16], HP);
            #pragma unroll
            for (int i = 0; i < 4; i++)
                #pragma unroll
                for (int j = 0; j < 2; j++)
                    wmma::mma_sync(acc[i][j], af[i], bf[j], acc[i][j]);
        }
    }
    __syncthreads();

    float* sC = dsmf;
    #pragma unroll
    for (int i = 0; i < 4; i++)
        #pragma unroll
        for (int j = 0; j < 2; j++)
            wmma::store_matrix_sync(&sC[(wm * 64 + i * 16) * EPIP + wn * 32 + j * 16],
                                    acc[i][j], EPIP, wmma::mem_row_major);
    __syncthreads();

    #pragma unroll
    for (int j = 0; j < 16; j++) {
        int idx = tid + j * 256;
        int r   = idx >> 5;
        int c4  = (idx & 31) << 2;
        float4 v = *(float4*)&sC[r * EPIP + c4];
        float4 b4 = *(const float4*)&bias[col0 + c4];
        v.x += b4.x; v.y += b4.y; v.z += b4.z; v.w += b4.w;
        if (EPI == 1) {
            float4 r4 = *(const float4*)&res[(size_t)(row0 + r) * N + col0 + c4];
            v.x += r4.x; v.y += r4.y; v.z += r4.z; v.w += r4.w;
            *(float4*)&((float*)Cv)[(size_t)(row0 + r) * N + col0 + c4] = v;
        } else if (EPI == 2) {
            v.x = v.x * normcdff(v.x);
            v.y = v.y * normcdff(v.y);
            v.z = v.z * normcdff(v.z);
            v.w = v.w * normcdff(v.w);
            __align__(8) __half2 t2[2];
            t2[0] = __floats2half2_rn(v.x, v.y);
            t2[1] = __floats2half2_rn(v.z, v.w);
            *(uint2*)&((__half*)Cv)[(size_t)(row0 + r) * N + col0 + c4] = *(uint2*)t2;
        } else {
            v.x *= oscale; v.y *= oscale; v.z *= oscale; v.w *= oscale;
            __align__(8) __half2 t2[2];
            t2[0] = __floats2half2_rn(v.x, v.y);
            t2[1] = __floats2half2_rn(v.z, v.w);
            *(uint2*)&((__half*)Cv)[(size_t)(row0 + r) * N + col0 + c4] = *(uint2*)t2;
        }
    }
}

// =====================================================================
// FP16 tensor-core flash attention (FA2-style), causal.
// grid (S/64, H, B), 128 threads = 4 warps; warp w owns q-rows 16w..16w+15.
// mma.sync m16n8k16; S/P in documented c-frag layout; P->A frag register
// identity; V via ldmatrix.x2.trans; K via ldmatrix.x2; Q via ldmatrix.x4.
// Q arrives pre-scaled by 1/sqrt(D). Output half (feeds Wo GEMM).
// =====================================================================
__global__ __launch_bounds__(128) void flash3(const __half* __restrict__ Q,
                                              const __half* __restrict__ K,
                                              const __half* __restrict__ V,
                                              __half* __restrict__ O)
{
    __shared__ __align__(16) __half sQ[64*64];
    __shared__ __align__(16) __half sK[64*64];
    __shared__ __align__(16) __half sV[64*64];

    int qt = blockIdx.x, h = blockIdx.y, b = blockIdx.z;
    int q0 = qt * 64;
    int tid = threadIdx.x;
    int w = tid >> 5, lane = tid & 31;
    int g = lane >> 2, c = lane & 3;

    // load Q tile (swizzled 16B chunks: ch ^ (row&7))
    size_t baseQ = ((size_t)(b * SS + q0)) * EE + h * DD;
    #pragma unroll
    for (int it = 0; it < 4; it++) {
        int f = tid + it * 128;
        int row = f >> 3, ch = f & 7;
        *(uint4*)&sQ[row * 64 + ((ch ^ (row & 7)) << 3)] =
            *(const uint4*)&Q[baseQ + (size_t)row * EE + ch * 8];
    }

    float m0 = -1e30f, m1 = -1e30f, l0 = 0.f, l1 = 0.f;
    float o[8][4];
    #pragma unroll
    for (int nt = 0; nt < 8; nt++)
        #pragma unroll
        for (int j = 0; j < 4; j++) o[nt][j] = 0.f;

    unsigned qb = su32(sQ), kb = su32(sK), vb = su32(sV);

    for (int ck = 0; ck <= qt; ck++) {
        __syncthreads();
        size_t baseK = ((size_t)(b * SS + ck * 64)) * EE + h * DD;
        #pragma unroll
        for (int it = 0; it < 4; it++) {
            int f = tid + it * 128;
            int row = f >> 3, ch = f & 7;
            int sw = row * 64 + ((ch ^ (row & 7)) << 3);
            *(uint4*)&sK[sw] = *(const uint4*)&K[baseK + (size_t)row * EE + ch * 8];
            *(uint4*)&sV[sw] = *(const uint4*)&V[baseK + (size_t)row * EE + ch * 8];
        }
        __syncthreads();

        // ---- S = Q K^T (fp32 accum) ----
        float s[8][4];
        #pragma unroll
        for (int nt = 0; nt < 8; nt++)
            #pragma unroll
            for (int j = 0; j < 4; j++) s[nt][j] = 0.f;

        #pragma unroll
        for (int kt = 0; kt < 4; kt++) {
            unsigned a[4];
            {
                int arow = w * 16 + (lane & 15);
                int ach  = 2 * kt + (lane >> 4);
                unsigned addr = qb + (unsigned)(arow * 64 + ((ach ^ (arow & 7)) << 3)) * 2u;
                asm volatile("ldmatrix.sync.aligned.m8n8.x4.shared.b16 {%0,%1,%2,%3}, [%4];"
                             : "=r"(a[0]), "=r"(a[1]), "=r"(a[2]), "=r"(a[3]) : "r"(addr));
            }
            #pragma unroll
            for (int nt = 0; nt < 8; nt++) {
                unsigned bbf[2];
                int krow = nt * 8 + (lane & 7);
                int kch  = 2 * kt + ((lane >> 3) & 1);
                unsigned addr = kb + (unsigned)(krow * 64 + ((kch ^ (krow & 7)) << 3)) * 2u;
                asm volatile("ldmatrix.sync.aligned.m8n8.x2.shared.b16 {%0,%1}, [%2];"
                             : "=r"(bbf[0]), "=r"(bbf[1]) : "r"(addr));
                asm volatile("mma.sync.aligned.m16n8k16.row.col.f32.f16.f16.f32 "
                             "{%0,%1,%2,%3}, {%4,%5,%6,%7}, {%8,%9}, {%0,%1,%2,%3};"
                             : "+f"(s[nt][0]), "+f"(s[nt][1]), "+f"(s[nt][2]), "+f"(s[nt][3])
                             : "r"(a[0]), "r"(a[1]), "r"(a[2]), "r"(a[3]),
                               "r"(bbf[0]), "r"(bbf[1]));
            }
        }

        // ---- causal mask on diagonal chunk ----
        if (ck == qt) {
            int r0 = w * 16 + g, r1 = r0 + 8;
            #pragma unroll
            for (int nt = 0; nt < 8; nt++) {
                int col = nt * 8 + 2 * c;
                if (col     > r0) s[nt][0] = -1e30f;
                if (col + 1 > r0) s[nt][1] = -1e30f;
                if (col     > r1) s[nt][2] = -1e30f;
                if (col + 1 > r1) s[nt][3] = -1e30f;
            }
        }

        // ---- online softmax (rows r0 = w*16+g, r1 = r0+8) ----
        float mx0 = s[0][0], mx1 = s[0][2];
        #pragma unroll
        for (int nt = 0; nt < 8; nt++) {
            mx0 = fmaxf(mx0, fmaxf(s[nt][0], s[nt][1]));
            mx1 = fmaxf(mx1, fmaxf(s[nt][2], s[nt][3]));
        }
        mx0 = fmaxf(mx0, __shfl_xor_sync(0xffffffffu, mx0, 1));
        mx0 = fmaxf(mx0, __shfl_xor_sync(0xffffffffu, mx0, 2));
        mx1 = fmaxf(mx1, __shfl_xor_sync(0xffffffffu, mx1, 1));
        mx1 = fmaxf(mx1, __shfl_xor_sync(0xffffffffu, mx1, 2));
        float mn0 = fmaxf(m0, mx0), mn1 = fmaxf(m1, mx1);
        float al0 = __expf(m0 - mn0), al1 = __expf(m1 - mn1);
        float sum0 = 0.f, sum1 = 0.f;
        #pragma unroll
        for (int nt = 0; nt < 8; nt++) {
            s[nt][0] = __expf(s[nt][0] - mn0);
            s[nt][1] = __expf(s[nt][1] - mn0);
            s[nt][2] = __expf(s[nt][2] - mn1);
            s[nt][3] = __expf(s[nt][3] - mn1);
            sum0 += s[nt][0] + s[nt][1];
            sum1 += s[nt][2] + s[nt][3];
        }
        sum0 += __shfl_xor_sync(0xffffffffu, sum0, 1);
        sum0 += __shfl_xor_sync(0xffffffffu, sum0, 2);
        sum1 += __shfl_xor_sync(0xffffffffu, sum1, 1);
        sum1 += __shfl_xor_sync(0xffffffffu, sum1, 2);
        l0 = l0 * al0 + sum0;
        l1 = l1 * al1 + sum1;
        m0 = mn0; m1 = mn1;
        #pragma unroll
        for (int nt = 0; nt < 8; nt++) {
            o[nt][0] *= al0; o[nt][1] *= al0;
            o[nt][2] *= al1; o[nt][3] *= al1;
        }

        // ---- O += P V  (P from S registers; V b-frags via ldmatrix.trans) ----
        #pragma unroll
        for (int kt = 0; kt < 4; kt++) {
            unsigned pa[4];
            pa[0] = h2pack(s[2*kt][0],     s[2*kt][1]);
            pa[1] = h2pack(s[2*kt][2],     s[2*kt][3]);
            pa[2] = h2pack(s[2*kt + 1][0], s[2*kt + 1][1]);
            pa[3] = h2pack(s[2*kt + 1][2], s[2*kt + 1][3]);
            #pragma unroll
            for (int nt = 0; nt < 8; nt++) {
                unsigned bbf[2];
                int vrow = kt * 16 + (lane & 15);
                unsigned addr = vb + (unsigned)(vrow * 64 + ((nt ^ (vrow & 7)) << 3)) * 2u;
                asm volatile("ldmatrix.sync.aligned.m8n8.x2.trans.shared.b16 {%0,%1}, [%2];"
                             : "=r"(bbf[0]), "=r"(bbf[1]) : "r"(addr));
                asm volatile("mma.sync.aligned.m16n8k16.row.col.f32.f16.f16.f32 "
                             "{%0,%1,%2,%3}, {%4,%5,%6,%7}, {%8,%9}, {%0,%1,%2,%3};"
                             : "+f"(o[nt][0]), "+f"(o[nt][1]), "+f"(o[nt][2]), "+f"(o[nt][3])
                             : "r"(pa[0]), "r"(pa[1]), "r"(pa[2]), "r"(pa[3]),
                               "r"(bbf[0]), "r"(bbf[1]));
            }
        }
    }

    // ---- write out (half) ----
    float i0 = 1.f / l0, i1 = 1.f / l1;
    int r0 = w * 16 + g;
    size_t base0 = ((size_t)(b * SS + q0 + r0)) * EE + h * DD;
    size_t base1 = base0 + (size_t)8 * EE;
    #pragma unroll
    for (int nt = 0; nt < 8; nt++) {
        int d = nt * 8 + 2 * c;
        __half2 h0 = __floats2half2_rn(o[nt][0] * i0, o[nt][1] * i0);
        __half2 h1 = __floats2half2_rn(o[nt][2] * i1, o[nt][3] * i1);
        *(__half2*)&O[base0 + d] = h0;
        *(__half2*)&O[base1 + d] = h1;
    }
}

// ---------------- launch ----------------
extern "C" void kernel_launch(void* const* d_in, const int* in_sizes, int n_in,
                              void* d_out, int out_size)
{
    (void)in_sizes; (void)n_in; (void)out_size;
    const float* x     = (const float*)d_in[0];
    const float* ln1_g = (const float*)d_in[2];
    const float* ln1_b = (const float*)d_in[3];
    const float* Wq    = (const float*)d_in[4];
    const float* bq    = (const float*)d_in[5];
    const float* Wk    = (const float*)d_in[6];
    const float* bk    = (const float*)d_in[7];
    const float* Wv    = (const float*)d_in[8];
    const float* bv    = (const float*)d_in[9];
    const float* Wo    = (const float*)d_in[10];
    const float* bo    = (const float*)d_in[11];
    const float* ln2_g = (const float*)d_in[12];
    const float* ln2_b = (const float*)d_in[13];
    const float* W1    = (const float*)d_in[14];
    const float* b1    = (const float*)d_in[15];
    const float* W2    = (const float*)d_in[16];
    const float* b2    = (const float*)d_in[17];
    float* out = (float*)d_out;

    void* p;
    __half *lnh, *qh, *kh, *vh, *ctxh, *midh, *wh;
    float *x1;
    cudaGetSymbolAddress(&p, g_lnh);  lnh  = (__half*)p;
    cudaGetSymbolAddress(&p, g_qh);   qh   = (__half*)p;
    cudaGetSymbolAddress(&p, g_kh);   kh   = (__half*)p;
    cudaGetSymbolAddress(&p, g_vh);   vh   = (__half*)p;
    cudaGetSymbolAddress(&p, g_ctxh); ctxh = (__half*)p;
    cudaGetSymbolAddress(&p, g_x1);   x1   = (float*)p;
    cudaGetSymbolAddress(&p, g_midh); midh = (__half*)p;
    cudaGetSymbolAddress(&p, g_wh);   wh   = (__half*)p;

    const int M1 = 1024 * 1024;
    __half* wq2 = wh;
    __half* wk2 = wh + 1 * M1;
    __half* wv2 = wh + 2 * M1;
    __half* wo2 = wh + 3 * M1;
    __half* w12 = wh + 4 * M1;
    __half* w22 = wh + 8 * M1;

    cudaFuncSetAttribute(gemmh<0>, cudaFuncAttributeMaxDynamicSharedMemorySize, GH_SMEM);
    cudaFuncSetAttribute(gemmh<1>, cudaFuncAttributeMaxDynamicSharedMemorySize, GH_SMEM);
    cudaFuncSetAttribute(gemmh<2>, cudaFuncAttributeMaxDynamicSharedMemorySize, GH_SMEM);

    dim3 gE(EE / 128, MM / 128);   // (8, 64)
    dim3 gF(FF / 128, MM / 128);   // (32, 64)

    // 0) convert weights to fp16
    cvt_kernel<<<512, 256>>>(Wq, wq2, M1 / 4);
    cvt_kernel<<<512, 256>>>(Wk, wk2, M1 / 4);
    cvt_kernel<<<512, 256>>>(Wv, wv2, M1 / 4);
    cvt_kernel<<<512, 256>>>(Wo, wo2, M1 / 4);
    cvt_kernel<<<1024, 256>>>(W1, w12, M1);
    cvt_kernel<<<1024, 256>>>(W2, w22, M1);

    // 1) ln1 (half out)
    ln_kernel<<<MM, 256>>>(x, ln1_g, ln1_b, lnh);
    // 2) QKV projections -> half; Q pre-scaled by 1/sqrt(D)=0.125
    gemmh<0><<<gE, 256, GH_SMEM>>>(lnh, wq2, bq, nullptr, qh, MM, EE, EE, 0.125f);
    gemmh<0><<<gE, 256, GH_SMEM>>>(lnh, wk2, bk, nullptr, kh, MM, EE, EE, 1.0f);
    gemmh<0><<<gE, 256, GH_SMEM>>>(lnh, wv2, bv, nullptr, vh, MM, EE, EE, 1.0f);
    // 3) attention (tensor cores, half out)
    flash3<<<dim3(SS / 64, HH, BB), 128>>>(qh, kh, vh, ctxh);
    // 4) output projection + bias + residual -> x1 (fp32)
    gemmh<1><<<gE, 256, GH_SMEM>>>(ctxh, wo2, bo, x, x1, MM, EE, EE, 1.0f);
    // 5) ln2 (half out)
    ln_kernel<<<MM, 256>>>(x1, ln2_g, ln2_b, lnh);
    // 6) FFN
    gemmh<2><<<gF, 256, GH_SMEM>>>(lnh, w12, b1, nullptr, midh, MM, FF, EE, 1.0f);
    gemmh<1><<<gE, 256, GH_SMEM>>>(midh, w22, b2, x1, out, MM, EE, FF, 1.0f);
}